// round 1
// baseline (speedup 1.0000x reference)
#include <cuda_runtime.h>

// Problem constants (fixed shapes for this problem)
#define NROIS 1024
#define CCH   512
#define HH    38
#define WW    50
#define HWSZ  (HH * WW)         // 1900
#define PRE   14                // pooling_size * 2
#define PS    7

#define PAIRS_PER_ROUND 4       // 4 float2 tiles -> 8 channels per round
#define CH_PER_ROUND    (PAIRS_PER_ROUND * 2)
#define THREADS         256
#define TILE_F2         (38 * 51)   // worst-case tile cells (stride padded odd)

struct RoiParams {
    int   x0c[PRE], x1c[PRE];       // clipped col indices, relative to clo
    float wx0[PRE], wx1[PRE];
    int   y0r[PRE], y1r[PRE];       // clipped row indices, relative to rlo
    float wy0[PRE], wy1[PRE];
    int   rlo, clo, nrows, ncols, stride;
};

__device__ __forceinline__ float grid_coord(float lo, float hi, float L, int j) {
    // Mirrors: t0=(hi-lo)/L; t2=(lo+hi-L)/L; base=-1+j*(2/13); g=t0*base+t2; i=(g+1)*0.5*L
    float t0 = (hi - lo) / L;
    float t2 = (lo + hi - L) / L;
    float base = -1.0f + (float)j * (2.0f / 13.0f);
    float g = t0 * base + t2;
    return (g + 1.0f) * 0.5f * L;
}

__global__ __launch_bounds__(THREADS)
void crop_pool_kernel(const float* __restrict__ bottom,
                      const float* __restrict__ rois,
                      float* __restrict__ out)
{
    extern __shared__ float2 smem[];   // PAIRS_PER_ROUND * TILE_F2 float2
    __shared__ RoiParams P;

    const int roi = blockIdx.x;
    const int tid = threadIdx.x;

    // ---- Phase 0: per-ROI interpolation params (threads 0..27) ----
    if (tid < 2 * PRE) {
        const int isY = (tid >= PRE);
        const int j   = isY ? (tid - PRE) : tid;
        const float lo = rois[roi * 5 + (isY ? 2 : 1)] * (1.0f / 16.0f);
        const float hi = rois[roi * 5 + (isY ? 4 : 3)] * (1.0f / 16.0f);
        const float Lf = isY ? (float)(HH - 1) : (float)(WW - 1);
        const int   Li = isY ? (HH - 1) : (WW - 1);

        float ic = grid_coord(lo, hi, Lf, j);
        float f  = floorf(ic);
        float a  = ic - f;
        int i0 = (int)f;
        int i1 = i0 + 1;
        int i0c = min(max(i0, 0), Li);
        int i1c = min(max(i1, 0), Li);
        float w0 = (i0 >= 0 && i0 <= Li) ? (1.0f - a) : 0.0f;
        float w1 = (i1 >= 0 && i1 <= Li) ? a : 0.0f;

        // lower corner of the bounding box (same for every thread of this axis)
        float ic0 = grid_coord(lo, hi, Lf, 0);
        int lo0 = min(max((int)floorf(ic0), 0), Li);

        if (!isY) {
            P.x0c[j] = i0c - lo0;  P.x1c[j] = i1c - lo0;
            P.wx0[j] = w0;         P.wx1[j] = w1;
            if (j == 0)  P.clo = lo0;
            if (j == 13) { int nc = i1c - lo0 + 1; P.ncols = nc; P.stride = nc | 1; }
        } else {
            P.y0r[j] = i0c - lo0;  P.y1r[j] = i1c - lo0;
            P.wy0[j] = w0;         P.wy1[j] = w1;
            if (j == 0)  P.rlo = lo0;
            if (j == 13) P.nrows = i1c - lo0 + 1;
        }
    }
    __syncthreads();

    const int stride = P.stride;
    const int nrows  = P.nrows;
    const int ncols  = P.ncols;
    const int rlo    = P.rlo;
    const int clo    = P.clo;

    // ---- compute-side lane mapping ----
    const int warp   = tid >> 5;
    const int lane   = tid & 31;
    const int pair   = warp >> 1;      // 0..3 : which float2 tile this warp samples
    const int half   = warp & 1;       // 0 -> py 0..3, 1 -> py 4..6
    const int jy_sub = lane >> 4;      // 0/1: which pre-pool row of the 2x2 window
    const int jxl    = lane & 15;      // pre-pool column (active when < 14)
    const bool jx_ok = (jxl < PRE);

    const int   cx0 = jx_ok ? P.x0c[jxl] : 0;
    const int   cx1 = jx_ok ? P.x1c[jxl] : 0;
    const float wx0 = jx_ok ? P.wx0[jxl] : 0.0f;
    const float wx1 = jx_ok ? P.wx1[jxl] : 0.0f;

    int   ry0s[4], ry1s[4];
    float wy0r[4], wy1r[4];
#pragma unroll
    for (int i = 0; i < 4; i++) {
        int py = half * 4 + i;
        if (py < PS) {
            int jy = 2 * py + jy_sub;
            ry0s[i] = P.y0r[jy] * stride;
            ry1s[i] = P.y1r[jy] * stride;
            wy0r[i] = P.wy0[jy];
            wy1r[i] = P.wy1[jy];
        } else {
            ry0s[i] = 0; ry1s[i] = 0; wy0r[i] = 0.0f; wy1r[i] = 0.0f;
        }
    }

    const bool store_lane = (jy_sub == 0) && ((jxl & 1) == 0) && jx_ok;
    const int  px = jxl >> 1;
    const int  niter = half ? 3 : 4;

    // ---- load-side lane mapping ----
    const int lp    = tid >> 6;        // which tile this thread helps load
    const int sub   = tid & 63;
    const int lrow0 = sub >> 5;
    const int lcol0 = sub & 31;

    const float2* tile = smem + pair * TILE_F2;

    for (int cb = 0; cb < CCH; cb += CH_PER_ROUND) {
        // -- coalesced tile load: 2 channels interleaved as float2 --
        {
            const int c0 = cb + lp * 2;
            const float* g0 = bottom + c0 * HWSZ;
            const float* g1 = g0 + HWSZ;
            float2* t = smem + lp * TILE_F2;
            for (int r = lrow0; r < nrows; r += 2) {
                const int gb = (rlo + r) * WW + clo;
                const int tb = r * stride;
                for (int col = lcol0; col < ncols; col += 32) {
                    t[tb + col] = make_float2(__ldg(g0 + gb + col), __ldg(g1 + gb + col));
                }
            }
        }
        __syncthreads();

        // -- sample + pool: one LDS.64 = one corner for 2 channels --
        const int cpair = cb + pair * 2;
        float* outp = out + ((size_t)roi * CCH + cpair) * (PS * PS);

#pragma unroll
        for (int i = 0; i < 4; i++) {
            if (i >= niter) break;   // uniform across warp
            float2 v00 = tile[ry0s[i] + cx0];
            float2 v01 = tile[ry0s[i] + cx1];
            float2 v10 = tile[ry1s[i] + cx0];
            float2 v11 = tile[ry1s[i] + cx1];

            float sx = wy0r[i] * (wx0 * v00.x + wx1 * v01.x)
                     + wy1r[i] * (wx0 * v10.x + wx1 * v11.x);
            float sy = wy0r[i] * (wx0 * v00.y + wx1 * v01.y)
                     + wy1r[i] * (wx0 * v10.y + wx1 * v11.y);

            // max over jx pair (lanes jx, jx^1), then over jy pair (lanes ^16)
            float ox = fmaxf(sx, __shfl_xor_sync(0xffffffffu, sx, 1));
            float oy = fmaxf(sy, __shfl_xor_sync(0xffffffffu, sy, 1));
            ox = fmaxf(ox, __shfl_xor_sync(0xffffffffu, ox, 16));
            oy = fmaxf(oy, __shfl_xor_sync(0xffffffffu, oy, 16));

            if (store_lane) {
                int py = half * 4 + i;
                outp[py * PS + px]            = ox;
                outp[PS * PS + py * PS + px]  = oy;
            }
        }
        __syncthreads();
    }
}

extern "C" void kernel_launch(void* const* d_in, const int* in_sizes, int n_in,
                              void* d_out, int out_size)
{
    const float* bottom = (const float*)d_in[0];
    const float* rois   = (const float*)d_in[1];
    float* out = (float*)d_out;

    const size_t smem_bytes = (size_t)PAIRS_PER_ROUND * TILE_F2 * sizeof(float2);
    cudaFuncSetAttribute(crop_pool_kernel,
                         cudaFuncAttributeMaxDynamicSharedMemorySize,
                         (int)smem_bytes);
    crop_pool_kernel<<<NROIS, THREADS, smem_bytes>>>(bottom, rois, out);
}

// round 2
// speedup vs baseline: 2.0119x; 2.0119x over previous
#include <cuda_runtime.h>

// Fixed problem shapes
#define NROIS 1024
#define CCH   512
#define HH    38
#define WW    50
#define HWSZ  (HH * WW)         // 1900
#define PRE   14                // pooling_size * 2
#define PS    7

#define THREADS   256
#define PAIRS     4             // 4 float2 tiles -> 8 channels per round
#define CHPR      (PAIRS * 2)
#define ROUNDS    (CCH / CHPR)  // 64
#define MAXLVL    28            // 14 samples x 2 corners
#define CELLS_MAX (MAXLVL * MAXLVL)   // 784

struct Params {
    // final compact-index interp params
    int   cl0[PRE], cl1[PRE];       // x level indices per sample
    float wx0[PRE], wx1[PRE];
    int   rl0[PRE], rl1[PRE];       // y level indices per sample
    float wy0[PRE], wy1[PRE];
    // temporaries (absolute clipped indices)
    int   sx0[PRE], sx1[PRE];
    int   sy0[PRE], sy1[PRE];
    unsigned char xmark[WW], ymark[HH];
    short xinv[WW], yinv[HH];
    short xlvl[MAXLVL], ylvl[MAXLVL];
    int   nlx, nly, ncells;
    int   cellg[CELLS_MAX];         // global offsets of compact cells
};

__device__ __forceinline__ float grid_coord(float lo, float hi, float L, int j) {
    float t0 = (hi - lo) / L;
    float t2 = (lo + hi - L) / L;
    float base = -1.0f + (float)j * (2.0f / 13.0f);
    float g = t0 * base + t2;
    return (g + 1.0f) * 0.5f * L;
}

// One warp builds the sorted-unique level list from a mark array (S <= 50).
__device__ __forceinline__ void build_levels(const unsigned char* mark, int S,
                                             short* inv, short* lvl, int* nOut,
                                             int lane) {
    int m0 = (lane < S) ? (int)mark[lane] : 0;
    int m1 = (lane + 32 < S) ? (int)mark[lane + 32] : 0;
    unsigned b0 = __ballot_sync(0xffffffffu, m0 != 0);
    unsigned b1 = __ballot_sync(0xffffffffu, m1 != 0);
    unsigned lm = (1u << lane) - 1u;
    if (m0) { int idx = __popc(b0 & lm); inv[lane] = (short)idx; lvl[idx] = (short)lane; }
    if (m1) { int idx = __popc(b0) + __popc(b1 & lm); inv[lane + 32] = (short)idx; lvl[idx] = (short)(lane + 32); }
    if (lane == 0) *nOut = __popc(b0) + __popc(b1);
}

__global__ __launch_bounds__(THREADS)
void crop_pool_kernel(const float* __restrict__ bottom,
                      const float* __restrict__ rois,
                      float* __restrict__ out)
{
    extern __shared__ float2 buf[];    // [2][PAIRS][CELLS_MAX]
    __shared__ Params P;

    const int roi  = blockIdx.x;
    const int tid  = threadIdx.x;
    const int warp = tid >> 5;
    const int lane = tid & 31;

    // ---- Phase A: zero marks + per-axis sample corner computation ----
    if (tid < WW)                       P.xmark[tid] = 0;
    if (tid >= 64 && tid < 64 + HH)     P.ymark[tid - 64] = 0;

    if (tid < 2 * PRE) {
        const int isY = (tid >= PRE);
        const int j   = isY ? (tid - PRE) : tid;
        const float lo = rois[roi * 5 + (isY ? 2 : 1)] * (1.0f / 16.0f);
        const float hi = rois[roi * 5 + (isY ? 4 : 3)] * (1.0f / 16.0f);
        const float Lf = isY ? (float)(HH - 1) : (float)(WW - 1);
        const int   Li = isY ? (HH - 1) : (WW - 1);

        float ic = grid_coord(lo, hi, Lf, j);
        float f  = floorf(ic);
        float a  = ic - f;
        int i0 = (int)f;
        int i1 = i0 + 1;
        int i0c = min(max(i0, 0), Li);
        int i1c = min(max(i1, 0), Li);
        float w0 = (i0 >= 0 && i0 <= Li) ? (1.0f - a) : 0.0f;
        float w1 = (i1 >= 0 && i1 <= Li) ? a : 0.0f;

        if (!isY) {
            P.sx0[j] = i0c; P.sx1[j] = i1c; P.wx0[j] = w0; P.wx1[j] = w1;
        } else {
            P.sy0[j] = i0c; P.sy1[j] = i1c; P.wy0[j] = w0; P.wy1[j] = w1;
        }
    }
    __syncthreads();

    // ---- Phase B: mark needed rows/cols ----
    if (tid < PRE) {
        P.xmark[P.sx0[tid]] = 1; P.xmark[P.sx1[tid]] = 1;
    } else if (tid < 2 * PRE) {
        int j = tid - PRE;
        P.ymark[P.sy0[j]] = 1; P.ymark[P.sy1[j]] = 1;
    }
    __syncthreads();

    // ---- Phase C: build level lists (warp-ballot prefix) ----
    if (warp == 0) build_levels(P.xmark, WW, P.xinv, P.xlvl, &P.nlx, lane);
    if (warp == 1) build_levels(P.ymark, HH, P.yinv, P.ylvl, &P.nly, lane);
    __syncthreads();

    // ---- Phase D: convert sample corners to level indices ----
    if (tid < PRE) {
        P.cl0[tid] = P.xinv[P.sx0[tid]];
        P.cl1[tid] = P.xinv[P.sx1[tid]];
    } else if (tid < 2 * PRE) {
        int j = tid - PRE;
        P.rl0[j] = P.yinv[P.sy0[j]];
        P.rl1[j] = P.yinv[P.sy1[j]];
    }
    if (tid == 0) P.ncells = P.nlx * P.nly;
    __syncthreads();

    const int nlx    = P.nlx;
    const int ncells = P.ncells;

    // ---- Phase E: precompute compact-cell global offsets ----
    for (int c = tid; c < ncells; c += THREADS) {
        int r = c / nlx;
        int x = c - r * nlx;
        P.cellg[c] = (int)P.ylvl[r] * WW + (int)P.xlvl[x];
    }
    __syncthreads();

    // ---- compute-side lane mapping (fixed per thread) ----
    const int pair   = warp >> 1;      // which float2 tile this warp samples
    const int half   = warp & 1;       // 0 -> py 0..3, 1 -> py 4..6
    const int jy_sub = lane >> 4;      // 0/1: pre-pool row within 2x2 window
    const int jxl    = lane & 15;      // pre-pool column (valid when < 14)
    const bool jx_ok = (jxl < PRE);

    const int   cx0 = jx_ok ? P.cl0[jxl] : 0;
    const int   cx1 = jx_ok ? P.cl1[jxl] : 0;
    const float wx0 = jx_ok ? P.wx0[jxl] : 0.0f;
    const float wx1 = jx_ok ? P.wx1[jxl] : 0.0f;

    int   ry0s[4], ry1s[4];
    float wy0r[4], wy1r[4];
#pragma unroll
    for (int i = 0; i < 4; i++) {
        int py = half * 4 + i;
        if (py < PS) {
            int jy = 2 * py + jy_sub;
            ry0s[i] = P.rl0[jy] * nlx;
            ry1s[i] = P.rl1[jy] * nlx;
            wy0r[i] = P.wy0[jy];
            wy1r[i] = P.wy1[jy];
        } else {
            ry0s[i] = 0; ry1s[i] = 0; wy0r[i] = 0.0f; wy1r[i] = 0.0f;
        }
    }

    const bool store_lane = (jy_sub == 0) && ((jxl & 1) == 0) && jx_ok;
    const int  px    = jxl >> 1;
    const int  niter = half ? 3 : 4;

    // ---- prologue: load round 0 ----
    {
        float2* dst = buf;   // buffer 0
        const float* gb = bottom;   // cb = 0
        for (int c = tid; c < ncells; c += THREADS) {
            int gi = P.cellg[c];
            const float* g = gb + gi;
#pragma unroll
            for (int p = 0; p < PAIRS; p++) {
                dst[p * CELLS_MAX + c] =
                    make_float2(__ldg(g + (2 * p) * HWSZ), __ldg(g + (2 * p + 1) * HWSZ));
            }
        }
    }
    __syncthreads();

    float* outp_base = out + (size_t)roi * CCH * (PS * PS) + pair * 2 * (PS * PS);

    for (int r = 0; r < ROUNDS; r++) {
        // -- prefetch round r+1 into the other buffer --
        if (r + 1 < ROUNDS) {
            float2* dst = buf + ((r + 1) & 1) * (PAIRS * CELLS_MAX);
            const float* gb = bottom + (size_t)(r + 1) * CHPR * HWSZ;
            for (int c = tid; c < ncells; c += THREADS) {
                int gi = P.cellg[c];
                const float* g = gb + gi;
#pragma unroll
                for (int p = 0; p < PAIRS; p++) {
                    dst[p * CELLS_MAX + c] =
                        make_float2(__ldg(g + (2 * p) * HWSZ), __ldg(g + (2 * p + 1) * HWSZ));
                }
            }
        }

        // -- compute round r --
        const float2* tile = buf + (r & 1) * (PAIRS * CELLS_MAX) + pair * CELLS_MAX;
        float* outp = outp_base + (size_t)r * CHPR * (PS * PS);

#pragma unroll
        for (int i = 0; i < 4; i++) {
            if (i >= niter) break;   // uniform within warp
            float2 v00 = tile[ry0s[i] + cx0];
            float2 v01 = tile[ry0s[i] + cx1];
            float2 v10 = tile[ry1s[i] + cx0];
            float2 v11 = tile[ry1s[i] + cx1];

            float sx = wy0r[i] * (wx0 * v00.x + wx1 * v01.x)
                     + wy1r[i] * (wx0 * v10.x + wx1 * v11.x);
            float sy = wy0r[i] * (wx0 * v00.y + wx1 * v01.y)
                     + wy1r[i] * (wx0 * v10.y + wx1 * v11.y);

            float ox = fmaxf(sx, __shfl_xor_sync(0xffffffffu, sx, 1));
            float oy = fmaxf(sy, __shfl_xor_sync(0xffffffffu, sy, 1));
            ox = fmaxf(ox, __shfl_xor_sync(0xffffffffu, ox, 16));
            oy = fmaxf(oy, __shfl_xor_sync(0xffffffffu, oy, 16));

            if (store_lane) {
                int py = half * 4 + i;
                outp[py * PS + px]           = ox;
                outp[PS * PS + py * PS + px] = oy;
            }
        }
        __syncthreads();
    }
}

extern "C" void kernel_launch(void* const* d_in, const int* in_sizes, int n_in,
                              void* d_out, int out_size)
{
    const float* bottom = (const float*)d_in[0];
    const float* rois   = (const float*)d_in[1];
    float* out = (float*)d_out;

    const size_t smem_bytes = (size_t)2 * PAIRS * CELLS_MAX * sizeof(float2);  // 50176
    cudaFuncSetAttribute(crop_pool_kernel,
                         cudaFuncAttributeMaxDynamicSharedMemorySize,
                         (int)smem_bytes);
    crop_pool_kernel<<<NROIS, THREADS, smem_bytes>>>(bottom, rois, out);
}

// round 3
// speedup vs baseline: 4.9111x; 2.4410x over previous
#include <cuda_runtime.h>

// Fixed problem shapes
#define NROIS 1024
#define CCH   512
#define HH    38
#define WW    50
#define HWSZ  (HH * WW)          // 1900
#define PRE   14                 // pooling_size * 2
#define PS    7

#define THREADS  256
#define NWARPS   (THREADS / 32)
#define SOUT_PAD 516             // pad 14-wide win rows to avoid LDS conflicts

// Transposed feature map: [cell = y*W + x][channel], 3.9 MB scratch.
__device__ __align__(16) float g_tr[HWSZ * CCH];

// ---------------- transpose kernel: [C][H*W] -> [H*W][C] ----------------
__global__ __launch_bounds__(256)
void transpose_kernel(const float* __restrict__ bottom)
{
    __shared__ float t[32][33];
    const int c0 = blockIdx.x * 32;     // cell tile base
    const int h0 = blockIdx.y * 32;     // channel tile base
    const int tx = threadIdx.x;         // 0..31
    const int ty = threadIdx.y;         // 0..7

#pragma unroll
    for (int i = 0; i < 4; i++) {
        int ch = h0 + ty + i * 8;
        int cc = c0 + tx;
        t[ty + i * 8][tx] = (cc < HWSZ) ? bottom[ch * HWSZ + cc] : 0.0f;
    }
    __syncthreads();
#pragma unroll
    for (int i = 0; i < 4; i++) {
        int cc = c0 + ty + i * 8;
        int ch = h0 + tx;
        if (cc < HWSZ) g_tr[cc * CCH + ch] = t[tx][ty + i * 8];
    }
}

// ---------------- main kernel: one CTA per ROI ----------------
__device__ __forceinline__ float grid_coord(float lo, float hi, float L, int j) {
    float t0 = (hi - lo) / L;
    float t2 = (lo + hi - L) / L;
    float base = -1.0f + (float)j * (2.0f / 13.0f);
    float g = t0 * base + t2;
    return (g + 1.0f) * 0.5f * L;
}

__global__ __launch_bounds__(THREADS)
void crop_pool_kernel(const float* __restrict__ rois,
                      float* __restrict__ out)
{
    __shared__ int   sxi[2][PRE];  __shared__ float sxw[2][PRE];
    __shared__ int   syi[2][PRE];  __shared__ float syw[2][PRE];
    __shared__ int4   soff[PRE * PRE];   // per-sample 4 corner offsets (floats)
    __shared__ float4 swt[PRE * PRE];    // per-sample 4 combined weights
    __shared__ __align__(16) float sout[14 * SOUT_PAD];

    const int roi = blockIdx.x;
    const int tid = threadIdx.x;

    // ---- Phase 1: per-axis corner indices + weights (threads 0..27) ----
    if (tid < 2 * PRE) {
        const int isY = (tid >= PRE);
        const int j   = isY ? (tid - PRE) : tid;
        const float lo = rois[roi * 5 + (isY ? 2 : 1)] * (1.0f / 16.0f);
        const float hi = rois[roi * 5 + (isY ? 4 : 3)] * (1.0f / 16.0f);
        const float Lf = isY ? (float)(HH - 1) : (float)(WW - 1);
        const int   Li = isY ? (HH - 1) : (WW - 1);

        float ic = grid_coord(lo, hi, Lf, j);
        float f  = floorf(ic);
        float a  = ic - f;
        int i0 = (int)f;
        int i1 = i0 + 1;
        int i0c = min(max(i0, 0), Li);
        int i1c = min(max(i1, 0), Li);
        float w0 = (i0 >= 0 && i0 <= Li) ? (1.0f - a) : 0.0f;
        float w1 = (i1 >= 0 && i1 <= Li) ? a : 0.0f;

        if (!isY) {
            sxi[0][j] = i0c; sxi[1][j] = i1c; sxw[0][j] = w0; sxw[1][j] = w1;
        } else {
            syi[0][j] = i0c; syi[1][j] = i1c; syw[0][j] = w0; syw[1][j] = w1;
        }
    }
    __syncthreads();

    // ---- Phase 2: per-sample packed corner offsets + weights (threads 0..195) ----
    if (tid < PRE * PRE) {
        const int jy = tid / PRE;
        const int jx = tid - jy * PRE;
        const int y0 = syi[0][jy], y1 = syi[1][jy];
        const int x0 = sxi[0][jx], x1 = sxi[1][jx];
        const float wy0 = syw[0][jy], wy1 = syw[1][jy];
        const float wx0 = sxw[0][jx], wx1 = sxw[1][jx];
        int4 o;
        o.x = (y0 * WW + x0) * CCH;
        o.y = (y0 * WW + x1) * CCH;
        o.z = (y1 * WW + x0) * CCH;
        o.w = (y1 * WW + x1) * CCH;
        float4 w;
        w.x = wy0 * wx0;
        w.y = wy0 * wx1;
        w.z = wy1 * wx0;
        w.w = wy1 * wx1;
        soff[tid] = o;
        swt[tid]  = w;
    }
    __syncthreads();

    const int warp = tid >> 5;
    const int lane = tid & 31;
    const float* __restrict__ trp = g_tr;

    // ---- Main loop: 4 chunks of pooled rows {0,1},{2,3},{4,5},{6} ----
    for (int pp = 0; pp < 4; pp++) {
        const int nwin  = (pp < 3) ? 14 : 7;     // windows in this chunk
        const int ntask = nwin * 4;              // x 4 channel blocks of 128

        for (int t = warp; t < ntask; t += NWARPS) {
            int win, chblk;
            if (pp < 3) { chblk = t / 14; win = t - chblk * 14; }
            else        { chblk = t / 7;  win = t - chblk * 7;  }
            const int py = pp * 2 + (win >= 7 ? 1 : 0);
            const int px = (win >= 7) ? (win - 7) : win;
            const int s00 = (2 * py) * PRE + 2 * px;
            const int choff = chblk * 128 + lane * 4;

            float4 m;
#pragma unroll
            for (int s = 0; s < 4; s++) {
                const int sid = s00 + (s >> 1) * PRE + (s & 1);
                const int4   o = soff[sid];
                const float4 w = swt[sid];
                float4 v0 = __ldg((const float4*)(trp + o.x + choff));
                float4 v1 = __ldg((const float4*)(trp + o.y + choff));
                float4 v2 = __ldg((const float4*)(trp + o.z + choff));
                float4 v3 = __ldg((const float4*)(trp + o.w + choff));
                float4 val;
                val.x = w.x * v0.x + w.y * v1.x + w.z * v2.x + w.w * v3.x;
                val.y = w.x * v0.y + w.y * v1.y + w.z * v2.y + w.w * v3.y;
                val.z = w.x * v0.z + w.y * v1.z + w.z * v2.z + w.w * v3.z;
                val.w = w.x * v0.w + w.y * v1.w + w.z * v2.w + w.w * v3.w;
                if (s == 0) m = val;
                else {
                    m.x = fmaxf(m.x, val.x);
                    m.y = fmaxf(m.y, val.y);
                    m.z = fmaxf(m.z, val.z);
                    m.w = fmaxf(m.w, val.w);
                }
            }
            *(float4*)(&sout[win * SOUT_PAD + choff]) = m;
        }
        __syncthreads();

        // ---- coalesced output: 56B-contiguous runs per channel ----
        float* ob = out + (size_t)roi * (CCH * PS * PS) + pp * 14;
        const int ne = nwin * CCH;
        if (pp < 3) {
            for (int e = tid; e < ne; e += THREADS) {
                int ch = e / 14;
                int o  = e - ch * 14;
                ob[ch * 49 + o] = sout[o * SOUT_PAD + ch];
            }
        } else {
            for (int e = tid; e < ne; e += THREADS) {
                int ch = e / 7;
                int o  = e - ch * 7;
                ob[ch * 49 + o] = sout[o * SOUT_PAD + ch];
            }
        }
        __syncthreads();
    }
}

extern "C" void kernel_launch(void* const* d_in, const int* in_sizes, int n_in,
                              void* d_out, int out_size)
{
    const float* bottom = (const float*)d_in[0];
    const float* rois   = (const float*)d_in[1];
    float* out = (float*)d_out;

    dim3 tgrid((HWSZ + 31) / 32, CCH / 32);
    transpose_kernel<<<tgrid, dim3(32, 8)>>>(bottom);
    crop_pool_kernel<<<NROIS, THREADS>>>(rois, out);
}

// round 4
// speedup vs baseline: 7.9077x; 1.6102x over previous
#include <cuda_runtime.h>
#include <cuda_fp16.h>

// Fixed problem shapes
#define NROIS 1024
#define CCH   512
#define HH    38
#define WW    50
#define HWSZ  (HH * WW)          // 1900
#define PRE   14                 // pooling_size * 2
#define PS    7

#define THREADS  256
#define NWARPS   (THREADS / 32)
#define SOUT_PAD 516             // pad 512-wide rows: bank stride 4 -> <=2-way LDS conflicts

// Transposed feature map in fp16: [cell = y*W + x][channel], 1.94 MB scratch (L2-resident).
__device__ __align__(16) __half g_trh[HWSZ * CCH];

// ---------------- transpose+convert kernel: [C][H*W] fp32 -> [H*W][C] fp16 ----------------
__global__ __launch_bounds__(256)
void transpose_kernel(const float* __restrict__ bottom)
{
    __shared__ float t[32][33];
    const int c0 = blockIdx.x * 32;     // cell tile base
    const int h0 = blockIdx.y * 32;     // channel tile base
    const int tx = threadIdx.x;         // 0..31
    const int ty = threadIdx.y;         // 0..7

#pragma unroll
    for (int i = 0; i < 4; i++) {
        int ch = h0 + ty + i * 8;
        int cc = c0 + tx;
        t[ty + i * 8][tx] = (cc < HWSZ) ? bottom[ch * HWSZ + cc] : 0.0f;
    }
    __syncthreads();
#pragma unroll
    for (int i = 0; i < 4; i++) {
        int cc = c0 + ty + i * 8;
        int ch = h0 + tx;
        if (cc < HWSZ) g_trh[cc * CCH + ch] = __float2half(t[tx][ty + i * 8]);
    }
}

// ---------------- main kernel: one CTA per ROI ----------------
__device__ __forceinline__ float grid_coord(float lo, float hi, float L, int j) {
    float t0 = (hi - lo) / L;
    float t2 = (lo + hi - L) / L;
    float base = -1.0f + (float)j * (2.0f / 13.0f);
    float g = t0 * base + t2;
    return (g + 1.0f) * 0.5f * L;
}

__global__ __launch_bounds__(THREADS)
void crop_pool_kernel(const float* __restrict__ rois,
                      float* __restrict__ out)
{
    __shared__ int   sxi[2][PRE];  __shared__ float sxw[2][PRE];
    __shared__ int   syi[2][PRE];  __shared__ float syw[2][PRE];
    __shared__ int4   soff[PRE * PRE];   // per-sample 4 corner offsets (half elements)
    __shared__ float4 swt[PRE * PRE];    // per-sample 4 combined weights
    __shared__ __align__(16) float sout[14 * SOUT_PAD];

    const int roi = blockIdx.x;
    const int tid = threadIdx.x;

    // ---- Phase 1: per-axis corner indices + weights (threads 0..27) ----
    if (tid < 2 * PRE) {
        const int isY = (tid >= PRE);
        const int j   = isY ? (tid - PRE) : tid;
        const float lo = rois[roi * 5 + (isY ? 2 : 1)] * (1.0f / 16.0f);
        const float hi = rois[roi * 5 + (isY ? 4 : 3)] * (1.0f / 16.0f);
        const float Lf = isY ? (float)(HH - 1) : (float)(WW - 1);
        const int   Li = isY ? (HH - 1) : (WW - 1);

        float ic = grid_coord(lo, hi, Lf, j);
        float f  = floorf(ic);
        float a  = ic - f;
        int i0 = (int)f;
        int i1 = i0 + 1;
        int i0c = min(max(i0, 0), Li);
        int i1c = min(max(i1, 0), Li);
        float w0 = (i0 >= 0 && i0 <= Li) ? (1.0f - a) : 0.0f;
        float w1 = (i1 >= 0 && i1 <= Li) ? a : 0.0f;

        if (!isY) {
            sxi[0][j] = i0c; sxi[1][j] = i1c; sxw[0][j] = w0; sxw[1][j] = w1;
        } else {
            syi[0][j] = i0c; syi[1][j] = i1c; syw[0][j] = w0; syw[1][j] = w1;
        }
    }
    __syncthreads();

    // ---- Phase 2: per-sample packed corner offsets + weights (threads 0..195) ----
    if (tid < PRE * PRE) {
        const int jy = tid / PRE;
        const int jx = tid - jy * PRE;
        const int y0 = syi[0][jy], y1 = syi[1][jy];
        const int x0 = sxi[0][jx], x1 = sxi[1][jx];
        const float wy0 = syw[0][jy], wy1 = syw[1][jy];
        const float wx0 = sxw[0][jx], wx1 = sxw[1][jx];
        int4 o;
        o.x = (y0 * WW + x0) * CCH;
        o.y = (y0 * WW + x1) * CCH;
        o.z = (y1 * WW + x0) * CCH;
        o.w = (y1 * WW + x1) * CCH;
        float4 w;
        w.x = wy0 * wx0;
        w.y = wy0 * wx1;
        w.z = wy1 * wx0;
        w.w = wy1 * wx1;
        soff[tid] = o;
        swt[tid]  = w;
    }
    __syncthreads();

    const int warp = tid >> 5;
    const int lane = tid & 31;
    const __half* __restrict__ trp = g_trh;

    // ---- Main loop: 4 chunks of pooled rows {0,1},{2,3},{4,5},{6} ----
    for (int pp = 0; pp < 4; pp++) {
        const int nwin  = (pp < 3) ? 14 : 7;     // windows in this chunk
        const int ntask = nwin * 2;              // x 2 channel blocks of 256

        for (int t = warp; t < ntask; t += NWARPS) {
            int win, chblk;
            if (pp < 3) { chblk = t / 14; win = t - chblk * 14; }
            else        { chblk = t / 7;  win = t - chblk * 7;  }
            const int py = pp * 2 + (win >= 7 ? 1 : 0);
            const int px = (win >= 7) ? (win - 7) : win;
            const int s00 = (2 * py) * PRE + 2 * px;
            const int choff = chblk * 256 + lane * 8;   // half-element offset, 8 ch/lane

            float m[8];
#pragma unroll
            for (int s = 0; s < 4; s++) {
                const int sid = s00 + (s >> 1) * PRE + (s & 1);
                const int4   o = soff[sid];
                const float4 w = swt[sid];
                uint4 c0 = __ldg((const uint4*)(trp + o.x + choff));
                uint4 c1 = __ldg((const uint4*)(trp + o.y + choff));
                uint4 c2 = __ldg((const uint4*)(trp + o.z + choff));
                uint4 c3 = __ldg((const uint4*)(trp + o.w + choff));
                const unsigned* u0 = (const unsigned*)&c0;
                const unsigned* u1 = (const unsigned*)&c1;
                const unsigned* u2 = (const unsigned*)&c2;
                const unsigned* u3 = (const unsigned*)&c3;
#pragma unroll
                for (int k = 0; k < 4; k++) {
                    float2 f0 = __half22float2(*(const __half2*)&u0[k]);
                    float2 f1 = __half22float2(*(const __half2*)&u1[k]);
                    float2 f2 = __half22float2(*(const __half2*)&u2[k]);
                    float2 f3 = __half22float2(*(const __half2*)&u3[k]);
                    float vx = w.x * f0.x + w.y * f1.x + w.z * f2.x + w.w * f3.x;
                    float vy = w.x * f0.y + w.y * f1.y + w.z * f2.y + w.w * f3.y;
                    if (s == 0) { m[2 * k] = vx; m[2 * k + 1] = vy; }
                    else {
                        m[2 * k]     = fmaxf(m[2 * k], vx);
                        m[2 * k + 1] = fmaxf(m[2 * k + 1], vy);
                    }
                }
            }
            float* sp = &sout[win * SOUT_PAD + choff];
            *(float4*)(sp)     = make_float4(m[0], m[1], m[2], m[3]);
            *(float4*)(sp + 4) = make_float4(m[4], m[5], m[6], m[7]);
        }
        __syncthreads();

        // ---- coalesced output: 56B-contiguous runs per channel ----
        float* ob = out + (size_t)roi * (CCH * PS * PS) + pp * 14;
        const int ne = nwin * CCH;
        if (pp < 3) {
            for (int e = tid; e < ne; e += THREADS) {
                int ch = e / 14;
                int o  = e - ch * 14;
                ob[ch * 49 + o] = sout[o * SOUT_PAD + ch];
            }
        } else {
            for (int e = tid; e < ne; e += THREADS) {
                int ch = e / 7;
                int o  = e - ch * 7;
                ob[ch * 49 + o] = sout[o * SOUT_PAD + ch];
            }
        }
        __syncthreads();
    }
}

extern "C" void kernel_launch(void* const* d_in, const int* in_sizes, int n_in,
                              void* d_out, int out_size)
{
    const float* bottom = (const float*)d_in[0];
    const float* rois   = (const float*)d_in[1];
    float* out = (float*)d_out;

    dim3 tgrid((HWSZ + 31) / 32, CCH / 32);
    transpose_kernel<<<tgrid, dim3(32, 8)>>>(bottom);
    crop_pool_kernel<<<NROIS, THREADS>>>(rois, out);
}